// round 1
// baseline (speedup 1.0000x reference)
#include <cuda_runtime.h>
#include <cuda_bf16.h>
#include <cstdint>

// ---------------------------------------------------------------------------
// OnlineLSTM: xg = inp @ W_ih^T + b_ih  (big GEMM, precomputed)
//             2048 sequential LSTM steps (persistent grid-resident kernel)
//             out = tanh(h_fin @ fc_w^T + fc_b); h_last/c_last at step 1023
// ---------------------------------------------------------------------------

#define WINDOW  2048
#define ISZ     4096
#define HID     1024
#define GATE4   4096      // 4*HID
#define METRIC  32
#define NCTA    128       // persistent CTAs for recurrence
#define UPB     8         // hidden units per CTA (NCTA*UPB = HID)

// Scratch (no cudaMalloc allowed)
__device__ float g_xg[WINDOW * GATE4];          // 32 MB
__device__ float g_h[2][HID];
__device__ volatile int g_flags[NCTA];

// ===========================================================================
// GEMM: C[t][r] = sum_k inp[t][k] * W_ih[r][k] + b_ih[r]
// 128x128 tile, K-tile 8, 256 threads, 8x8 micro-tile via fma.rn.f32x2
// ===========================================================================
#define BM 128
#define BN 128
#define BK 8
#define LDT (BM + 4)   // 132 floats, 528B row stride (16B multiple)

__device__ __forceinline__ unsigned long long dup_f32x2(float a) {
    unsigned long long r;
    unsigned int ai = __float_as_uint(a);
    asm("mov.b64 %0, {%1, %1};" : "=l"(r) : "r"(ai));
    return r;
}
__device__ __forceinline__ void fma2(unsigned long long& acc,
                                     unsigned long long a,
                                     unsigned long long b) {
    asm("fma.rn.f32x2 %0, %1, %2, %0;" : "+l"(acc) : "l"(a), "l"(b));
}

__global__ void __launch_bounds__(256) gemm_xg_kernel(
    const float* __restrict__ A,      // inp [2048,4096]
    const float* __restrict__ B,      // W_ih [4096,4096] (row = out gate, K contiguous)
    const float* __restrict__ bias,   // b_ih [4096]
    float* __restrict__ C)            // g_xg [2048,4096]
{
    __shared__ __align__(16) float As[BK][LDT];
    __shared__ __align__(16) float Bs[BK][LDT];

    const int tid = threadIdx.x;
    const int bm = blockIdx.y * BM;
    const int bn = blockIdx.x * BN;

    const int lr = tid >> 1;          // 0..127 row within tile
    const int lk = (tid & 1) * 4;     // 0 or 4
    const float* Aptr = A + (size_t)(bm + lr) * ISZ + lk;
    const float* Bptr = B + (size_t)(bn + lr) * ISZ + lk;

    const int tx = tid & 15;          // n dim
    const int ty = tid >> 4;          // m dim

    unsigned long long acc2[8][4];
#pragma unroll
    for (int i = 0; i < 8; i++)
#pragma unroll
        for (int j = 0; j < 4; j++) acc2[i][j] = 0ull;

    float4 av = *(const float4*)(Aptr);
    float4 bv = *(const float4*)(Bptr);

    for (int k0 = 0; k0 < ISZ; k0 += BK) {
        __syncthreads();
        As[lk + 0][lr] = av.x; As[lk + 1][lr] = av.y;
        As[lk + 2][lr] = av.z; As[lk + 3][lr] = av.w;
        Bs[lk + 0][lr] = bv.x; Bs[lk + 1][lr] = bv.y;
        Bs[lk + 2][lr] = bv.z; Bs[lk + 3][lr] = bv.w;
        __syncthreads();

        if (k0 + BK < ISZ) {
            av = *(const float4*)(Aptr + k0 + BK);
            bv = *(const float4*)(Bptr + k0 + BK);
        }

#pragma unroll
        for (int kk = 0; kk < BK; kk++) {
            float4 a0 = *(const float4*)&As[kk][ty * 8];
            float4 a1 = *(const float4*)&As[kk][ty * 8 + 4];
            ulonglong2 bq0 = *(const ulonglong2*)&Bs[kk][tx * 8];
            ulonglong2 bq1 = *(const ulonglong2*)&Bs[kk][tx * 8 + 4];
            unsigned long long b2[4] = {bq0.x, bq0.y, bq1.x, bq1.y};
            float a[8] = {a0.x, a0.y, a0.z, a0.w, a1.x, a1.y, a1.z, a1.w};
#pragma unroll
            for (int i = 0; i < 8; i++) {
                unsigned long long ad = dup_f32x2(a[i]);
#pragma unroll
                for (int j = 0; j < 4; j++) fma2(acc2[i][j], ad, b2[j]);
            }
        }
    }

    // epilogue: add bias, store
    float bcol[8];
#pragma unroll
    for (int j = 0; j < 8; j++) bcol[j] = bias[bn + tx * 8 + j];

#pragma unroll
    for (int i = 0; i < 8; i++) {
        float* crow = C + (size_t)(bm + ty * 8 + i) * GATE4 + bn + tx * 8;
#pragma unroll
        for (int j = 0; j < 4; j++) {
            unsigned int lo, hi;
            asm("mov.b64 {%0, %1}, %2;" : "=r"(lo), "=r"(hi) : "l"(acc2[i][j]));
            crow[2 * j]     = __uint_as_float(lo) + bcol[2 * j];
            crow[2 * j + 1] = __uint_as_float(hi) + bcol[2 * j + 1];
        }
    }
}

// ===========================================================================
// Init: reset barrier flags, seed h buffer with h1
// ===========================================================================
__global__ void init_kernel(const float* __restrict__ h1) {
    int i = threadIdx.x;   // 1024 threads
    if (i < NCTA) g_flags[i] = 0;
    g_h[0][i] = h1[i];
}

// ===========================================================================
// Persistent LSTM recurrence. 128 CTAs x 256 threads. Each CTA: 8 hidden
// units, 32 W_hh rows pinned in SMEM (128KB). Warp w owns unit (bid*8+w);
// its c lives in lane 0's register file. h exchanged via double-buffered
// global array + flag-array grid barrier (one per step).
// ===========================================================================
__device__ __forceinline__ float sigf(float x) {
    return 1.0f / (1.0f + __expf(-x));
}

__global__ void __launch_bounds__(256, 1) lstm_rec_kernel(
    const float* __restrict__ W_hh,   // [4096,1024]
    const float* __restrict__ c1,     // [1024]
    const float* __restrict__ b_hh,   // [4096]
    float* __restrict__ out,          // d_out
    int writeHC)
{
    extern __shared__ __align__(16) float smem[];
    float* Wsm = smem;                 // 32*1024 floats
    float* hsm = smem + 32 * HID;      // 1024 floats

    const int tid = threadIdx.x;
    const int bid = blockIdx.x;
    const int w = tid >> 5;            // warp id = unit within CTA
    const int l = tid & 31;
    const int j = bid * UPB + w;       // global hidden unit

    // --- stage this CTA's 32 W_hh rows into SMEM (row lr = g*8+u) ---
    for (int i = tid; i < 32 * (HID / 4); i += 256) {
        int lrow = i >> 8;             // /256 float4 per row
        int kq = i & 255;
        int g = lrow >> 3, u = lrow & 7;
        ((float4*)Wsm)[lrow * 256 + kq] =
            __ldg((const float4*)(W_hh + (size_t)(g * HID + bid * UPB + u) * HID) + kq);
    }

    float b0 = 0.f, b1 = 0.f, b2 = 0.f, b3 = 0.f, c = 0.f;
    if (l == 0) {
        b0 = b_hh[j];            b1 = b_hh[HID + j];
        b2 = b_hh[2 * HID + j];  b3 = b_hh[3 * HID + j];
        c = c1[j];
    }
    __syncthreads();

    for (int t = 0; t < WINDOW; t++) {
        const int p = t & 1;

        // broadcast h into SMEM (L2-only loads: L1 is stale inside this kernel)
        ((float4*)hsm)[tid] = __ldcg(((const float4*)g_h[p]) + tid);

        float xg0 = 0.f, xg1 = 0.f, xg2 = 0.f, xg3 = 0.f;
        if (l == 0) {
            const float* xr = g_xg + (size_t)t * GATE4 + j;
            xg0 = __ldg(xr);           xg1 = __ldg(xr + HID);
            xg2 = __ldg(xr + 2 * HID); xg3 = __ldg(xr + 3 * HID);
        }
        __syncthreads();

        float4 h4[8];
#pragma unroll
        for (int jj = 0; jj < 8; jj++) h4[jj] = ((const float4*)hsm)[l + 32 * jj];

        float acc[4] = {0.f, 0.f, 0.f, 0.f};
#pragma unroll
        for (int g = 0; g < 4; g++) {
            const float4* wr = (const float4*)(Wsm + (g * 8 + w) * HID);
#pragma unroll
            for (int jj = 0; jj < 8; jj++) {
                float4 wv = wr[l + 32 * jj];
                acc[g] += wv.x * h4[jj].x + wv.y * h4[jj].y
                        + wv.z * h4[jj].z + wv.w * h4[jj].w;
            }
        }
#pragma unroll
        for (int off = 16; off; off >>= 1) {
            acc[0] += __shfl_xor_sync(0xffffffffu, acc[0], off);
            acc[1] += __shfl_xor_sync(0xffffffffu, acc[1], off);
            acc[2] += __shfl_xor_sync(0xffffffffu, acc[2], off);
            acc[3] += __shfl_xor_sync(0xffffffffu, acc[3], off);
        }

        if (l == 0) {
            float pi = acc[0] + xg0 + b0;
            float pf = acc[1] + xg1 + b1;
            float pg = acc[2] + xg2 + b2;
            float po = acc[3] + xg3 + b3;
            float ig = sigf(pi), fg = sigf(pf), gg = tanhf(pg), og = sigf(po);
            c = fg * c + ig * gg;
            float hn = og * tanhf(c);
            g_h[p ^ 1][j] = hn;
            if (writeHC && t == 1023) {          // STRIDE-1
                out[METRIC + j] = hn;
                out[METRIC + HID + j] = c;
            }
        }
        __syncthreads();

        // ---- grid barrier (flag array, no atomics) ----
        if (tid == 0) {
            __threadfence();
            g_flags[bid] = t + 1;
        }
        if (tid < NCTA) {
            while (g_flags[tid] <= t) { }
        }
        __syncthreads();
    }
}

// ===========================================================================
// out = tanh(h_fin @ fc_w^T + fc_b). h_fin = g_h[0] (2048 even steps).
// 32 warps, one per output metric.
// ===========================================================================
__global__ void fc_kernel(const float* __restrict__ fc_w,
                          const float* __restrict__ fc_b,
                          float* __restrict__ out)
{
    const int w = threadIdx.x >> 5;    // 0..31
    const int l = threadIdx.x & 31;
    const float4* hv = (const float4*)g_h[0];
    const float4* wv = (const float4*)(fc_w + (size_t)w * HID);
    float s = 0.f;
#pragma unroll
    for (int jj = 0; jj < 8; jj++) {
        float4 a = hv[l + 32 * jj];
        float4 b = wv[l + 32 * jj];
        s += a.x * b.x + a.y * b.y + a.z * b.z + a.w * b.w;
    }
#pragma unroll
    for (int off = 16; off; off >>= 1) s += __shfl_xor_sync(0xffffffffu, s, off);
    if (l == 0) out[w] = tanhf(s + fc_b[w]);
}

// ===========================================================================
// launch
// ===========================================================================
extern "C" void kernel_launch(void* const* d_in, const int* in_sizes, int n_in,
                              void* d_out, int out_size) {
    const float* inp  = (const float*)d_in[0];
    const float* h1   = (const float*)d_in[1];
    const float* c1   = (const float*)d_in[2];
    const float* W_ih = (const float*)d_in[3];
    const float* W_hh = (const float*)d_in[4];
    // b_ih = d_in[5] used in GEMM; b_hh = d_in[6] in recurrence
    const float* b_ih = (const float*)d_in[5];
    const float* b_hh = (const float*)d_in[6];
    const float* fc_w = (const float*)d_in[7];
    const float* fc_b = (const float*)d_in[8];
    float* out = (float*)d_out;

    int writeHC = (out_size >= METRIC + 2 * HID) ? 1 : 0;

    float* xg_ptr = nullptr;
    cudaGetSymbolAddress((void**)&xg_ptr, g_xg);

    // Phase 1: xg GEMM
    dim3 ggrid(GATE4 / BN, WINDOW / BM);
    gemm_xg_kernel<<<ggrid, 256>>>(inp, W_ih, b_ih, xg_ptr);

    // Phase 1b: init h buffer + barrier flags
    init_kernel<<<1, HID>>>(h1);

    // Phase 2: persistent recurrence (128KB W + 4KB h in dynamic smem)
    size_t smem_bytes = (32 * HID + HID) * sizeof(float);
    static int attr_set = 0;
    if (!attr_set) {
        cudaFuncSetAttribute(lstm_rec_kernel,
                             cudaFuncAttributeMaxDynamicSharedMemorySize,
                             (int)smem_bytes);
        attr_set = 1;
    }
    lstm_rec_kernel<<<NCTA, 256, smem_bytes>>>(W_hh, c1, b_hh, out, writeHC);

    // Phase 3: fc epilogue
    fc_kernel<<<1, METRIC * 32>>>(fc_w, fc_b, out);
}